// round 9
// baseline (speedup 1.0000x reference)
#include <cuda_runtime.h>
#include <math.h>

#define FDIM 128
#define GMAX 50000
#define CAP  192
#define OVF_MAX 4096
#define DEPTH 8

// ---------------- device scratch (zero-initialized .bss; self-restoring) ----------------
__device__ int g_cnt[GMAX];                 // per-segment node count (restored to 0 by pool)
__device__ int g_perm[(size_t)GMAX * CAP];  // bucketed node indices
__device__ int g_ovf[OVF_MAX];              // overflow node list (normally empty)
__device__ int g_novf;                      // overflow count (reset by pool's last block)
__device__ int g_is64;                      // seg dtype flag (written by scatter)
__device__ int g_done;                      // block-arrival ticket (reset by last block)

__device__ __forceinline__ float tanh_fast(float x) {
    float r;
    asm("tanh.approx.f32 %0, %1;" : "=f"(r) : "f"(x));
    return r;
}

__device__ __forceinline__ void facc(float4& a, const float4& v) {
    a.x += v.x; a.y += v.y; a.z += v.z; a.w += v.w;
}

__device__ __forceinline__ unsigned smem_u32(const void* p) {
    return (unsigned)__cvta_generic_to_shared(p);
}

#define CP_ASYNC16(smaddr, gptr) \
    asm volatile("cp.async.cg.shared.global [%0], [%1], 16;" :: "r"(smaddr), "l"(gptr))
#define CP_COMMIT() \
    asm volatile("cp.async.commit_group;" ::: "memory")
#define CP_WAIT(n) \
    asm volatile("cp.async.wait_group %0;" :: "n"(n) : "memory")

// ---------------- kernel 1: scatter nodes into per-segment buckets ----------------
__global__ void __launch_bounds__(256) scatter_kernel(const void* __restrict__ seg, int N) {
    __shared__ int s_is64;
    if (threadIdx.x == 0) {
        // int64 ids < 2^32 have zero high words; 64 random int32 ids all-zero: p ~ 0
        const unsigned int* w = (const unsigned int*)seg;
        unsigned int acc = 0;
        #pragma unroll
        for (int k = 0; k < 64; k++) acc |= w[2 * k + 1];
        s_is64 = (acc == 0u) ? 1 : 0;
        if (blockIdx.x == 0) g_is64 = s_is64;
    }
    __syncthreads();
    const int is64 = s_is64;

    int base = (blockIdx.x * blockDim.x + threadIdx.x) * 4;
    if (base >= N) return;
    int cnt = min(4, N - base);

    int ids[4];
    if (cnt == 4) {
        if (is64) {
            const longlong2* p = (const longlong2*)((const long long*)seg + base);
            longlong2 v0 = __ldg(p), v1 = __ldg(p + 1);
            ids[0] = (int)v0.x; ids[1] = (int)v0.y; ids[2] = (int)v1.x; ids[3] = (int)v1.y;
        } else {
            int4 v = __ldg((const int4*)((const int*)seg + base));
            ids[0] = v.x; ids[1] = v.y; ids[2] = v.z; ids[3] = v.w;
        }
    } else {
        for (int j = 0; j < cnt; j++)
            ids[j] = is64 ? (int)((const long long*)seg)[base + j]
                          : ((const int*)seg)[base + j];
    }

    #pragma unroll
    for (int j = 0; j < 4; j++) {
        if (j >= cnt) break;
        int s = ids[j];
        int slot = atomicAdd(&g_cnt[s], 1);
        if (slot < CAP) {
            g_perm[(size_t)s * CAP + slot] = base + j;
        } else {
            int o = atomicAdd(&g_novf, 1);
            if (o < OVF_MAX) g_ovf[o] = base + j;
        }
    }
}

// ---------------- kernel 2: cp.async-pipelined gather-pool + fused MLP ----------------
// One segment per warp, independent warps. Depth-8 cp.async ring: outstanding
// loads live in smem, not registers, so ~8 rows/warp in flight at ~40 regs.
// Each lane owns its 16B slice of every row -> no cross-lane sync in the loop.
__global__ void __launch_bounds__(256) pool_mlp_kernel(
    const float* __restrict__ h,
    const void*  __restrict__ seg,
    const float* __restrict__ W1,   // [128,128] row-major: W1[k][c]
    const float* __restrict__ b1,   // [128]
    const float* __restrict__ W2,   // [128]
    const float* __restrict__ b2,   // [1]
    float* __restrict__ y, int G)
{
    __shared__ float ring[8][DEPTH][FDIM];      // 8 warps x 8 rows x 512B = 32 KB
    const int warp = threadIdx.x >> 5;
    const int lane = threadIdx.x & 31;
    const int g = blockIdx.x * 8 + warp;
    const int nov = g_novf;                     // read before any block resets it

    if (g < G) {
        const int n = g_cnt[g];
        if (lane == 0) g_cnt[g] = 0;            // self-restore for next replay
        const int nn = min(n, CAP);
        const int* pm = &g_perm[(size_t)g * CAP];

        // issue row j (always commits a group; cp.async only when j valid)
        auto issue = [&](int j, int id) {
            if (j < nn) {
                unsigned sa = smem_u32(&ring[warp][j & (DEPTH - 1)][lane * 4]);
                const float* src = h + (size_t)id * FDIM + lane * 4;
                CP_ASYNC16(sa, src);
            }
            CP_COMMIT();
        };

        // prologue: indices + issues for rows 0..7
        int4 q0 = make_int4(0, 0, 0, 0), q1 = q0;
        if (nn > 0) q0 = __ldg((const int4*)pm);
        if (nn > 4) q1 = __ldg((const int4*)(pm + 4));
        issue(0, q0.x); issue(1, q0.y); issue(2, q0.z); issue(3, q0.w);
        issue(4, q1.x); issue(5, q1.y); issue(6, q1.z); issue(7, q1.w);

        float4 a0 = make_float4(0.f, 0.f, 0.f, 0.f);
        float4 a1 = a0;

        const int B = (nn + 3) >> 2;            // 4-row batches
        for (int b = 0; b < B; b++) {
            const int r  = 4 * b;
            const int jb = r + 8;
            int4 qi = make_int4(0, 0, 0, 0);
            if (jb < nn) qi = __ldg((const int4*)(pm + jb));

            CP_WAIT(7);
            if (r < nn) facc(a0, *(const float4*)&ring[warp][r & 7][lane * 4]);
            issue(jb + 0, qi.x);

            CP_WAIT(7);
            if (r + 1 < nn) facc(a1, *(const float4*)&ring[warp][(r + 1) & 7][lane * 4]);
            issue(jb + 1, qi.y);

            CP_WAIT(7);
            if (r + 2 < nn) facc(a0, *(const float4*)&ring[warp][(r + 2) & 7][lane * 4]);
            issue(jb + 2, qi.z);

            CP_WAIT(7);
            if (r + 3 < nn) facc(a1, *(const float4*)&ring[warp][(r + 3) & 7][lane * 4]);
            issue(jb + 3, qi.w);
        }
        CP_WAIT(0);

        // overflow path (correctness safety net; empty for real data)
        if (nov > 0) {
            const int m = min(nov, OVF_MAX);
            const int is64 = g_is64;
            for (int k = 0; k < m; k++) {
                int nd = g_ovf[k];
                int s = is64 ? (int)((const long long*)seg)[nd]
                             : ((const int*)seg)[nd];
                if (s == g) {
                    float4 v = __ldg((const float4*)(h + (size_t)nd * FDIM) + lane);
                    facc(a0, v);
                }
            }
        }

        float4 acc;
        acc.x = a0.x + a1.x; acc.y = a0.y + a1.y;
        acc.z = a0.z + a1.z; acc.w = a0.w + a1.w;

        // stage pooled row in ring slot 0 for the GEMV broadcast
        *(float4*)&ring[warp][0][lane * 4] = acc;
        __syncwarp();

        // hidden[4l..4l+3] = tanh(b1 + pooled @ W1); y = hidden . W2 + b2
        float4 bb = __ldg((const float4*)b1 + lane);
        float h0 = bb.x, h1 = bb.y, h2 = bb.z, h3 = bb.w;
        const float4* W1v = (const float4*)W1;  // row k, chunk lane
        const float* sA = &ring[warp][0][0];

        #pragma unroll 4
        for (int k = 0; k < FDIM; k++) {
            float4 w = __ldg(W1v + k * 32 + lane);
            float pk = sA[k];
            h0 = fmaf(pk, w.x, h0);
            h1 = fmaf(pk, w.y, h1);
            h2 = fmaf(pk, w.z, h2);
            h3 = fmaf(pk, w.w, h3);
        }

        float4 w2 = __ldg((const float4*)W2 + lane);
        float p = tanh_fast(h0) * w2.x + tanh_fast(h1) * w2.y
                + tanh_fast(h2) * w2.z + tanh_fast(h3) * w2.w;

        #pragma unroll
        for (int off = 16; off; off >>= 1)
            p += __shfl_down_sync(0xffffffffu, p, off);
        if (lane == 0) y[g] = p + __ldg(b2);
    }

    // ---- elected last block resets overflow state for the next replay ----
    if (threadIdx.x == 0) {
        __threadfence();
        int t = atomicAdd(&g_done, 1);
        if (t == (int)gridDim.x - 1) {
            g_novf = 0;
            g_done = 0;
        }
    }
}

// ---------------- launch ----------------
extern "C" void kernel_launch(void* const* d_in, const int* in_sizes, int n_in,
                              void* d_out, int out_size) {
    const float* h   = (const float*)d_in[0];
    const void*  seg = d_in[1];
    const int N = in_sizes[0] / FDIM;
    const int G = out_size;          // OUT = 1

    int iw = -1;
    for (int i = 2; i < n_in; i++) {
        if (in_sizes[i] == FDIM * FDIM) { iw = i; break; }
    }
    const float* W1 = (const float*)d_in[iw];
    const float* b1 = (const float*)d_in[iw + 1];
    const float* W2 = (const float*)d_in[iw + 2];
    const float* b2 = (const float*)d_in[iw + 3];
    float* y = (float*)d_out;

    const int nodes_per_blk = 256 * 4;
    scatter_kernel<<<(N + nodes_per_blk - 1) / nodes_per_blk, 256>>>(seg, N);
    pool_mlp_kernel<<<(G + 7) / 8, 256>>>(h, seg, W1, b1, W2, b2, y, G);
}

// round 10
// speedup vs baseline: 1.1535x; 1.1535x over previous
#include <cuda_runtime.h>
#include <math.h>

#define FDIM 128
#define GMAX 50000

// ---------------- device scratch (zero-initialized .bss; self-restoring) ----------------
// g_pool starts zero (.bss); the MLP kernel re-zeroes it after consuming it,
// so every graph replay sees zeros again. L2-resident (25.6 MB << 126 MB L2).
__device__ float g_pool[(size_t)GMAX * FDIM];

__device__ __forceinline__ float tanh_fast(float x) {
    float r;
    asm("tanh.approx.f32 %0, %1;" : "=f"(r) : "f"(x));
    return r;
}

// ---------------- kernel 1: stream h in node order, scatter-add into L2 pool ----------------
// Perfectly coalesced, sequential h reads (row-buffer friendly). Each node row is
// reduced into pooled[seg] with fire-and-forget vector reductions (no return latency).
__global__ void __launch_bounds__(256) stream_pool_kernel(
    const float* __restrict__ h,
    const void*  __restrict__ seg,
    int N)
{
    __shared__ int s_is64;
    if (threadIdx.x == 0) {
        // int64 ids < 2^32 have zero high words; 64 random int32 ids all-zero: p ~ 0
        const unsigned int* w = (const unsigned int*)seg;
        unsigned int acc = 0;
        #pragma unroll
        for (int k = 0; k < 64; k++) acc |= w[2 * k + 1];
        s_is64 = (acc == 0u) ? 1 : 0;
    }
    __syncthreads();
    const int is64 = s_is64;

    const int warp = threadIdx.x >> 5;
    const int lane = threadIdx.x & 31;
    const int base = (blockIdx.x * 8 + warp) * 32;   // 32 consecutive nodes per warp
    if (base >= N) return;                           // uniform per warp
    const int cnt = min(32, N - base);

    // lane l holds seg id of node base+l (coalesced 128B/256B read)
    int sid = 0;
    if (lane < cnt) {
        sid = is64 ? (int)((const long long*)seg)[base + lane]
                   : ((const int*)seg)[base + lane];
    }

    // stream 32 rows: sequential LDG.128 (full warp = 512B contiguous), then
    // red.global.add.v4.f32 into the L2-resident pooled row (no return value).
    #pragma unroll 4
    for (int j = 0; j < 32; j++) {
        if (j >= cnt) break;
        const int s = __shfl_sync(0xffffffffu, sid, j);
        float4 v = __ldcs((const float4*)(h + (size_t)(base + j) * FDIM) + lane);
        float* dst = g_pool + (size_t)s * FDIM + lane * 4;
        asm volatile("red.global.add.v4.f32 [%0], {%1, %2, %3, %4};"
                     :: "l"(dst), "f"(v.x), "f"(v.y), "f"(v.z), "f"(v.w)
                     : "memory");
    }
}

// ---------------- kernel 2: MLP head (pooled -> y), 16 segments per block ----------------
// W1 element loaded once per 8 segments; pooled operand is an smem broadcast.
// After consuming its pooled tile, the block zeroes it for the next replay.
__global__ void __launch_bounds__(256) mlp_kernel(
    const float* __restrict__ W1,   // [128,128] row-major: W1[k][c]
    const float* __restrict__ b1,   // [128]
    const float* __restrict__ W2,   // [128]
    const float* __restrict__ b2,   // [1]
    float* __restrict__ y, int G)
{
    __shared__ float sp[16][FDIM];  // pooled tile (8 KB)
    __shared__ float sred[16][4];   // per-(seg, warp-in-half) partial dots

    const int gbase = blockIdx.x * 16;
    const int tid  = threadIdx.x;
    const int c    = tid & 127;     // column 0..127
    const int half = tid >> 7;      // 0 -> segs 0..7, 1 -> segs 8..15
    const int wih  = (tid >> 5) & 3;// warp index within half
    const int lane = tid & 31;

    // load pooled tile (contiguous, fully coalesced), then zero it in gmem
    {
        float4* src = (float4*)(g_pool + (size_t)gbase * FDIM);
        float4 t0 = src[tid];
        float4 t1 = src[tid + 256];
        ((float4*)sp)[tid]       = t0;
        ((float4*)sp)[tid + 256] = t1;
        const float4 z4 = make_float4(0.f, 0.f, 0.f, 0.f);
        src[tid]       = z4;        // self-restore for the next replay
        src[tid + 256] = z4;
    }
    __syncthreads();

    float bb = __ldg(b1 + c);
    float acc[8];
    #pragma unroll
    for (int s = 0; s < 8; s++) acc[s] = bb;

    const int r0 = half * 8;
    #pragma unroll 4
    for (int k = 0; k < FDIM; k++) {
        float wv = __ldg(W1 + k * FDIM + c);    // coalesced; one load -> 8 FMAs
        #pragma unroll
        for (int s = 0; s < 8; s++)
            acc[s] = fmaf(sp[r0 + s][k], wv, acc[s]);   // smem broadcast
    }

    float w2v = __ldg(W2 + c);
    #pragma unroll
    for (int s = 0; s < 8; s++) {
        float p = tanh_fast(acc[s]) * w2v;
        #pragma unroll
        for (int off = 16; off; off >>= 1)
            p += __shfl_down_sync(0xffffffffu, p, off);
        if (lane == 0) sred[r0 + s][wih] = p;
    }
    __syncthreads();

    if (tid < 16) {
        int g = gbase + tid;
        if (g < G)
            y[g] = sred[tid][0] + sred[tid][1] + sred[tid][2] + sred[tid][3]
                 + __ldg(b2);
    }
}

// ---------------- launch ----------------
extern "C" void kernel_launch(void* const* d_in, const int* in_sizes, int n_in,
                              void* d_out, int out_size) {
    const float* h   = (const float*)d_in[0];
    const void*  seg = d_in[1];
    const int N = in_sizes[0] / FDIM;
    const int G = out_size;          // OUT = 1

    int iw = -1;
    for (int i = 2; i < n_in; i++) {
        if (in_sizes[i] == FDIM * FDIM) { iw = i; break; }
    }
    const float* W1 = (const float*)d_in[iw];
    const float* b1 = (const float*)d_in[iw + 1];
    const float* W2 = (const float*)d_in[iw + 2];
    const float* b2 = (const float*)d_in[iw + 3];
    float* y = (float*)d_out;

    const int nodes_per_blk = 8 * 32;    // 8 warps x 32 nodes
    stream_pool_kernel<<<(N + nodes_per_blk - 1) / nodes_per_blk, 256>>>(h, seg, N);
    mlp_kernel<<<(G + 15) / 16, 256>>>(W1, b1, W2, b2, y, G);
}

// round 11
// speedup vs baseline: 1.1635x; 1.0087x over previous
#include <cuda_runtime.h>
#include <math.h>

#define FDIM 128
#define GMAX 50000

// ---------------- device scratch (zero-initialized .bss; self-restoring) ----------------
// g_pool starts zero (.bss); the MLP kernel re-zeroes it after consuming it,
// so every graph replay sees zeros again. L2-resident (25.6 MB << 126 MB L2).
__device__ float g_pool[(size_t)GMAX * FDIM];

__device__ __forceinline__ float tanh_fast(float x) {
    float r;
    asm("tanh.approx.f32 %0, %1;" : "=f"(r) : "f"(x));
    return r;
}

// ---------------- kernel 1: stream h in node order, scatter-add into L2 pool ----------------
// Perfectly coalesced, sequential h reads (row-buffer friendly). Each node row is
// reduced into pooled[seg] with fire-and-forget vector reductions (no return latency).
__global__ void __launch_bounds__(256) stream_pool_kernel(
    const float* __restrict__ h,
    const void*  __restrict__ seg,
    int N)
{
    __shared__ int s_is64;
    if (threadIdx.x == 0) {
        // int64 ids < 2^32 have zero high words; 64 random int32 ids all-zero: p ~ 0
        const unsigned int* w = (const unsigned int*)seg;
        unsigned int acc = 0;
        #pragma unroll
        for (int k = 0; k < 64; k++) acc |= w[2 * k + 1];
        s_is64 = (acc == 0u) ? 1 : 0;
    }
    __syncthreads();
    const int is64 = s_is64;

    const int warp = threadIdx.x >> 5;
    const int lane = threadIdx.x & 31;
    const int base = (blockIdx.x * 8 + warp) * 32;   // 32 consecutive nodes per warp
    if (base >= N) return;                           // uniform per warp
    const int cnt = min(32, N - base);

    // lane l holds seg id of node base+l (coalesced read)
    int sid = 0;
    if (lane < cnt) {
        sid = is64 ? (int)((const long long*)seg)[base + lane]
                   : ((const int*)seg)[base + lane];
    }

    // stream 32 rows: sequential LDG.128 (full warp = 512B contiguous), then
    // red.global.add.v4.f32 into the L2-resident pooled row (no return value).
    #pragma unroll 4
    for (int j = 0; j < 32; j++) {
        if (j >= cnt) break;
        const int s = __shfl_sync(0xffffffffu, sid, j);
        float4 v = __ldcs((const float4*)(h + (size_t)(base + j) * FDIM) + lane);
        float* dst = g_pool + (size_t)s * FDIM + lane * 4;
        asm volatile("red.global.add.v4.f32 [%0], {%1, %2, %3, %4};"
                     :: "l"(dst), "f"(v.x), "f"(v.y), "f"(v.z), "f"(v.w)
                     : "memory");
    }
}

// ---------------- kernel 2: MLP head (pooled -> y), 16 segments per block ----------------
// Inner loop restructured for LDS economy: k unrolled by 4, pooled operand read
// as LDS.128 broadcast (2 LDS per k for 8 segments instead of 8 scalar LDS).
__global__ void __launch_bounds__(256) mlp_kernel(
    const float* __restrict__ W1,   // [128,128] row-major: W1[k][c]
    const float* __restrict__ b1,   // [128]
    const float* __restrict__ W2,   // [128]
    const float* __restrict__ b2,   // [1]
    float* __restrict__ y, int G)
{
    __shared__ float sp[16][FDIM];  // pooled tile (8 KB), rows 512B (16B-aligned)
    __shared__ float sred[16][4];   // per-(seg, warp-in-half) partial dots

    const int gbase = blockIdx.x * 16;
    const int tid  = threadIdx.x;
    const int c    = tid & 127;     // column 0..127
    const int half = tid >> 7;      // 0 -> segs 0..7, 1 -> segs 8..15
    const int wih  = (tid >> 5) & 3;// warp index within half
    const int lane = tid & 31;

    // load pooled tile (contiguous, fully coalesced), then zero it in gmem
    {
        float4* src = (float4*)(g_pool + (size_t)gbase * FDIM);
        float4 t0 = src[tid];
        float4 t1 = src[tid + 256];
        ((float4*)sp)[tid]       = t0;
        ((float4*)sp)[tid + 256] = t1;
        const float4 z4 = make_float4(0.f, 0.f, 0.f, 0.f);
        src[tid]       = z4;        // self-restore for the next replay
        src[tid + 256] = z4;
    }
    __syncthreads();

    float bb = __ldg(b1 + c);
    float acc[8];
    #pragma unroll
    for (int s = 0; s < 8; s++) acc[s] = bb;

    const int r0 = half * 8;
    #pragma unroll 8
    for (int k = 0; k < FDIM; k += 4) {
        // 4 coalesced W1 loads (one per k in the group)
        float wv0 = __ldg(W1 + (k + 0) * FDIM + c);
        float wv1 = __ldg(W1 + (k + 1) * FDIM + c);
        float wv2 = __ldg(W1 + (k + 2) * FDIM + c);
        float wv3 = __ldg(W1 + (k + 3) * FDIM + c);
        #pragma unroll
        for (int s = 0; s < 8; s++) {
            // LDS.128 broadcast: all lanes read the same 16B -> conflict-free
            float4 ps = *(const float4*)&sp[r0 + s][k];
            acc[s] = fmaf(ps.x, wv0, acc[s]);
            acc[s] = fmaf(ps.y, wv1, acc[s]);
            acc[s] = fmaf(ps.z, wv2, acc[s]);
            acc[s] = fmaf(ps.w, wv3, acc[s]);
        }
    }

    float w2v = __ldg(W2 + c);
    #pragma unroll
    for (int s = 0; s < 8; s++) {
        float p = tanh_fast(acc[s]) * w2v;
        #pragma unroll
        for (int off = 16; off; off >>= 1)
            p += __shfl_down_sync(0xffffffffu, p, off);
        if (lane == 0) sred[r0 + s][wih] = p;
    }
    __syncthreads();

    if (tid < 16) {
        int g = gbase + tid;
        if (g < G)
            y[g] = sred[tid][0] + sred[tid][1] + sred[tid][2] + sred[tid][3]
                 + __ldg(b2);
    }
}

// ---------------- launch ----------------
extern "C" void kernel_launch(void* const* d_in, const int* in_sizes, int n_in,
                              void* d_out, int out_size) {
    const float* h   = (const float*)d_in[0];
    const void*  seg = d_in[1];
    const int N = in_sizes[0] / FDIM;
    const int G = out_size;          // OUT = 1

    int iw = -1;
    for (int i = 2; i < n_in; i++) {
        if (in_sizes[i] == FDIM * FDIM) { iw = i; break; }
    }
    const float* W1 = (const float*)d_in[iw];
    const float* b1 = (const float*)d_in[iw + 1];
    const float* W2 = (const float*)d_in[iw + 2];
    const float* b2 = (const float*)d_in[iw + 3];
    float* y = (float*)d_out;

    const int nodes_per_blk = 8 * 32;    // 8 warps x 32 nodes
    stream_pool_kernel<<<(N + nodes_per_blk - 1) / nodes_per_blk, 256>>>(h, seg, N);
    mlp_kernel<<<(G + 15) / 16, 256>>>(W1, b1, W2, b2, y, G);
}